// round 6
// baseline (speedup 1.0000x reference)
#include <cuda_runtime.h>

#define N_NODE 4096
#define KNN 32
#define HIDDEN 128
#define RMS_EPS 1e-5f
#define TABLE_N 4096
#define NQ 8
#define NBUCK 256
#define CAP 192

__device__ float g_table[TABLE_N];
__device__ float4 g_pos4[N_NODE];

typedef unsigned long long u64;

static __device__ __forceinline__ u64 ullmin2(u64 a, u64 b) { return (b < a) ? b : a; }

// ---------------------------------------------------------------------------
// Kernel 1: table of s(u), u = r/(1+r), uniform grid; prep (pos -> float4)
// fused in the same launch as extra blocks.
// ---------------------------------------------------------------------------
__global__ void __launch_bounds__(128, 8)
table_prep_kernel(const float* __restrict__ pos,
                  const float* __restrict__ t,
                  const float* __restrict__ W1,
                  const float* __restrict__ b1,
                  const float* __restrict__ g1,
                  const float* __restrict__ W2,
                  const float* __restrict__ b2,
                  const float* __restrict__ g2,
                  const float* __restrict__ W3,
                  const float* __restrict__ b3) {
    const int tid = threadIdx.x;

    if (blockIdx.x >= TABLE_N / 16) {
        int j = (blockIdx.x - TABLE_N / 16) * 128 + tid;
        if (j < N_NODE)
            g_pos4[j] = make_float4(pos[3 * j], pos[3 * j + 1], pos[3 * j + 2], 0.0f);
        return;
    }

    __shared__ float h1s[4][HIDDEN * 4];
    __shared__ float sa[128], sc[128], sg1[128], sg2[128], sW3[128];
    __shared__ float sABC[3];
    __shared__ float sred[12];

    const int w = tid >> 5, lane = tid & 31;

    {
        const int k = tid;
        float t0 = t[0];
        float a = W1[2 * k];
        float c = fmaf(t0, W1[2 * k + 1], b1[k]);
        sa[k] = a; sc[k] = c;
        sg1[k] = g1[k]; sg2[k] = g2[k]; sW3[k] = W3[k];
        float pa = a * a, pb = a * c, pc = c * c;
        #pragma unroll
        for (int off = 16; off > 0; off >>= 1) {
            pa += __shfl_down_sync(0xffffffffu, pa, off);
            pb += __shfl_down_sync(0xffffffffu, pb, off);
            pc += __shfl_down_sync(0xffffffffu, pc, off);
        }
        if (lane == 0) { sred[w] = pa; sred[4 + w] = pb; sred[8 + w] = pc; }
    }
    __syncthreads();
    if (tid == 0) {
        const float inv = 1.0f / HIDDEN;
        sABC[0] = (sred[0] + sred[1] + sred[2] + sred[3]) * inv;
        sABC[1] = (sred[4] + sred[5] + sred[6] + sred[7]) * inv;
        sABC[2] = (sred[8] + sred[9] + sred[10] + sred[11]) * inv;
    }
    __syncthreads();

    const float A = sABC[0], Bc = sABC[1], C = sABC[2];
    const int s0 = blockIdx.x * 16 + w * 4;
    float* h1b = h1s[w];

    #pragma unroll
    for (int q = 0; q < 4; q++) {
        float u = (float)(s0 + q) * (1.0f / (float)(TABLE_N - 1));
        float om = 1.0f - u;
        float r = (om > 1e-8f) ? (u / om) : 1e9f;
        float den = fmaf(fmaf(r, A, 2.0f * Bc), r, C) + RMS_EPS;
        float scl = rsqrtf(den);
        #pragma unroll
        for (int p = 0; p < 4; p++) {
            int k = lane + 32 * p;
            float x = fmaf(r, sa[k], sc[k]);
            float v = x * scl * sg1[k];
            float h = v * (1.0f / (1.0f + __expf(-v)));
            h1b[k * 4 + q] = h;
        }
    }
    __syncwarp();

    float acc[4][4];
    #pragma unroll
    for (int p = 0; p < 4; p++)
        #pragma unroll
        for (int q = 0; q < 4; q++) acc[p][q] = 0.0f;

    const float4* wr0 = (const float4*)(W2 + (lane)      * HIDDEN);
    const float4* wr1 = (const float4*)(W2 + (lane + 32) * HIDDEN);
    const float4* wr2 = (const float4*)(W2 + (lane + 64) * HIDDEN);
    const float4* wr3 = (const float4*)(W2 + (lane + 96) * HIDDEN);
    #pragma unroll 2
    for (int kk = 0; kk < 32; kk++) {
        float4 w0 = __ldg(wr0 + kk), w1 = __ldg(wr1 + kk);
        float4 w2 = __ldg(wr2 + kk), w3 = __ldg(wr3 + kk);
        float w0a[4] = {w0.x, w0.y, w0.z, w0.w};
        float w1a[4] = {w1.x, w1.y, w1.z, w1.w};
        float w2a[4] = {w2.x, w2.y, w2.z, w2.w};
        float w3a[4] = {w3.x, w3.y, w3.z, w3.w};
        #pragma unroll
        for (int kq = 0; kq < 4; kq++) {
            float4 hv = *(const float4*)(h1b + (4 * kk + kq) * 4);
            float hva[4] = {hv.x, hv.y, hv.z, hv.w};
            #pragma unroll
            for (int q = 0; q < 4; q++) {
                acc[0][q] = fmaf(w0a[kq], hva[q], acc[0][q]);
                acc[1][q] = fmaf(w1a[kq], hva[q], acc[1][q]);
                acc[2][q] = fmaf(w2a[kq], hva[q], acc[2][q]);
                acc[3][q] = fmaf(w3a[kq], hva[q], acc[3][q]);
            }
        }
    }

    #pragma unroll
    for (int p = 0; p < 4; p++) {
        float bb = b2[lane + 32 * p];
        #pragma unroll
        for (int q = 0; q < 4; q++) acc[p][q] += bb;
    }

    float scl2[4];
    #pragma unroll
    for (int q = 0; q < 4; q++) {
        float ss = 0.0f;
        #pragma unroll
        for (int p = 0; p < 4; p++) ss = fmaf(acc[p][q], acc[p][q], ss);
        #pragma unroll
        for (int off = 16; off > 0; off >>= 1)
            ss += __shfl_xor_sync(0xffffffffu, ss, off);
        scl2[q] = rsqrtf(ss * (1.0f / HIDDEN) + RMS_EPS);
    }

    float dot[4] = {0.0f, 0.0f, 0.0f, 0.0f};
    #pragma unroll
    for (int p = 0; p < 4; p++) {
        int m = lane + 32 * p;
        float g = sg2[m], w3v = sW3[m];
        #pragma unroll
        for (int q = 0; q < 4; q++) {
            float v = acc[p][q] * scl2[q] * g;
            float h = v * (1.0f / (1.0f + __expf(-v)));
            dot[q] = fmaf(w3v, h, dot[q]);
        }
    }
    #pragma unroll
    for (int q = 0; q < 4; q++) {
        #pragma unroll
        for (int off = 16; off > 0; off >>= 1)
            dot[q] += __shfl_xor_sync(0xffffffffu, dot[q], off);
    }
    if (lane == 0) {
        float bb3 = b3[0];
        #pragma unroll
        for (int q = 0; q < 4; q++) g_table[s0 + q] = dot[q] + bb3;
    }
}

// ---------------------------------------------------------------------------
// Kernel 2: fused kNN + eval. 8 warps = 8 queries per 256-thr block.
// Pass 1: exact per-warp 256-bucket (exponent) histogram, with
//         __match_any_sync leader-aggregated smem atomics (LSU relief).
// Scan -> rank-32 bucket B + base (exact, no retry).
// Pass 2: bucket<B edges accumulate s(r)*d; bucket==B -> small candidate
//         list; exact (bits,idx)-min extraction; rescan fallback if > CAP.
// ---------------------------------------------------------------------------
__global__ void __launch_bounds__(256, 5)
knn_eval_kernel(float* __restrict__ out) {
    __shared__ float4 tile[512];                 // 8 KB
    __shared__ unsigned hist[NQ][NBUCK];         // 8 KB
    __shared__ u64 cand[NQ][CAP];                // 12 KB
    __shared__ int ccnt[NQ];

    const int tid = threadIdx.x;
    const int w = tid >> 5, lane = tid & 31;
    const int i = blockIdx.x * NQ + w;
    const float4 pi = g_pos4[i];
    unsigned* myhist = hist[w];
    u64* mycand = cand[w];

    for (int b = lane; b < NBUCK; b += 32) myhist[b] = 0;
    if (lane == 0) ccnt[w] = 0;

    // ---- Pass 1: aggregated histogram ----
    for (int tb = 0; tb < 8; tb++) {
        __syncthreads();
        tile[tid]       = g_pos4[tb * 512 + tid];
        tile[tid + 256] = g_pos4[tb * 512 + 256 + tid];
        __syncthreads();
        #pragma unroll 4
        for (int it = 0; it < 16; it++) {
            int jl = it * 32 + lane;
            float4 q = tile[jl];
            float dx = pi.x - q.x, dy = pi.y - q.y, dz = pi.z - q.z;
            float d = fmaf(dx, dx, fmaf(dy, dy, dz * dz));
            int j = tb * 512 + jl;
            unsigned bits = (j == i) ? 0x7f800000u : __float_as_uint(d);
            unsigned bucket = bits >> 23;
            unsigned mmask = __match_any_sync(0xffffffffu, bucket);
            if ((int)(__ffs(mmask) - 1) == lane)
                atomicAdd(&myhist[bucket], (unsigned)__popc(mmask));
        }
    }
    __syncwarp();

    // ---- Scan 256 buckets; lane owns [lane*8, lane*8+8) ----
    const int b0 = lane * 8;
    unsigned hv[8];
    unsigned lsum = 0;
    #pragma unroll
    for (int q = 0; q < 8; q++) { hv[q] = myhist[b0 + q]; lsum += hv[q]; }
    unsigned run = lsum;
    #pragma unroll
    for (int off = 1; off < 32; off <<= 1) {
        unsigned v = __shfl_up_sync(0xffffffffu, run, off);
        if (lane >= off) run += v;
    }
    run -= lsum;  // exclusive prefix
    u64 pk = 0;
    {
        unsigned r2 = run;
        #pragma unroll
        for (int q = 0; q < 8; q++) {
            if (r2 < KNN && r2 + hv[q] >= KNN)
                pk = ((u64)(unsigned)(b0 + q) << 32) | r2;
            r2 += hv[q];
        }
    }
    #pragma unroll
    for (int off = 16; off > 0; off >>= 1) {
        u64 o = __shfl_xor_sync(0xffffffffu, pk, off);
        if (o > pk) pk = o;
    }
    const int B2 = (int)(pk >> 32);
    const int base = (int)(pk & 0xffffffffu);
    const unsigned hb2 = myhist[B2];
    __syncwarp();

    // ---- Pass 2 ----
    const float tscale = (float)(TABLE_N - 1);
    float sx = 0.0f, sy = 0.0f, sz = 0.0f;

    #define ACCUM_EDGE(_bits, _dx, _dy, _dz) do {                          \
        float _r = __uint_as_float(_bits);                                 \
        float _u = _r / (1.0f + _r);                                       \
        float _x = _u * tscale;                                            \
        int _i0 = (int)_x; if (_i0 > TABLE_N - 2) _i0 = TABLE_N - 2;       \
        float _f = _x - (float)_i0;                                        \
        float _s0 = g_table[_i0], _s1 = g_table[_i0 + 1];                  \
        float _sv = fmaf(_f, _s1 - _s0, _s0);                              \
        sx = fmaf(_dx, _sv, sx);                                           \
        sy = fmaf(_dy, _sv, sy);                                           \
        sz = fmaf(_dz, _sv, sz);                                           \
    } while (0)

    const bool small_bucket = (hb2 <= CAP);
    for (int tb = 0; tb < 8; tb++) {
        __syncthreads();
        tile[tid]       = g_pos4[tb * 512 + tid];
        tile[tid + 256] = g_pos4[tb * 512 + 256 + tid];
        __syncthreads();
        #pragma unroll 4
        for (int it = 0; it < 16; it++) {
            int jl = it * 32 + lane;
            float4 q = tile[jl];
            float dx = pi.x - q.x, dy = pi.y - q.y, dz = pi.z - q.z;
            float d = fmaf(dx, dx, fmaf(dy, dy, dz * dz));
            int j = tb * 512 + jl;
            unsigned bits = (j == i) ? 0x7f800000u : __float_as_uint(d);
            int bk = (int)(bits >> 23);
            if (bk < B2) {
                ACCUM_EDGE(bits, dx, dy, dz);
            } else if (bk == B2 && small_bucket) {
                int p = atomicAdd(&ccnt[w], 1);
                mycand[p] = ((u64)bits << 32) | (unsigned)j;
            }
        }
    }
    __syncwarp();

    // ---- Boundary bucket: extract (KNN - base) smallest by (bits, idx) ----
    const int need = KNN - base;
    if (small_bucket) {
        const int cn = ccnt[w];
        for (int s = 0; s < need; s++) {
            u64 best = ~0ull;
            for (int c = lane; c < cn; c += 32) best = ullmin2(best, mycand[c]);
            #pragma unroll
            for (int off = 16; off > 0; off >>= 1)
                best = ullmin2(best, __shfl_xor_sync(0xffffffffu, best, off));
            if (lane == 0) {
                unsigned bb = (unsigned)(best >> 32);
                int j = (int)(best & 0xffffffffu);
                float4 q = g_pos4[j];
                float dx = pi.x - q.x, dy = pi.y - q.y, dz = pi.z - q.z;
                ACCUM_EDGE(bb, dx, dy, dz);
            }
            for (int c = lane; c < cn; c += 32)
                if (mycand[c] == best) mycand[c] = ~0ull;
        }
    } else {
        // Fallback (probability ~0): direct rescan of boundary bucket
        u64 last = 0;
        for (int s = 0; s < need; s++) {
            u64 best = ~0ull;
            for (int j0 = lane; j0 < N_NODE; j0 += 32) {
                float4 q = g_pos4[j0];
                float dx = pi.x - q.x, dy = pi.y - q.y, dz = pi.z - q.z;
                float d = fmaf(dx, dx, fmaf(dy, dy, dz * dz));
                unsigned bits = (j0 == i) ? 0x7f800000u : __float_as_uint(d);
                if ((int)(bits >> 23) == B2) {
                    u64 key = ((u64)bits << 32) | (unsigned)j0;
                    if (key > last) best = ullmin2(best, key);
                }
            }
            #pragma unroll
            for (int off = 16; off > 0; off >>= 1)
                best = ullmin2(best, __shfl_xor_sync(0xffffffffu, best, off));
            if (lane == 0 && best != ~0ull) {
                unsigned bb = (unsigned)(best >> 32);
                int j = (int)(best & 0xffffffffu);
                float4 q = g_pos4[j];
                float dx = pi.x - q.x, dy = pi.y - q.y, dz = pi.z - q.z;
                ACCUM_EDGE(bb, dx, dy, dz);
            }
            last = best;
        }
    }
    #undef ACCUM_EDGE

    // ---- Warp reduce + write ----
    #pragma unroll
    for (int off = 16; off > 0; off >>= 1) {
        sx += __shfl_down_sync(0xffffffffu, sx, off);
        sy += __shfl_down_sync(0xffffffffu, sy, off);
        sz += __shfl_down_sync(0xffffffffu, sz, off);
    }
    if (lane == 0) {
        const float invK = 1.0f / (float)KNN;
        out[3 * i]     = pi.x + sx * invK;
        out[3 * i + 1] = pi.y + sy * invK;
        out[3 * i + 2] = pi.z + sz * invK;
    }
}

// ---------------------------------------------------------------------------
// Launch
// ---------------------------------------------------------------------------
extern "C" void kernel_launch(void* const* d_in, const int* in_sizes, int n_in,
                              void* d_out, int out_size) {
    const float* pos = (const float*)d_in[0];
    const float* t   = (const float*)d_in[1];
    const float* W1  = (const float*)d_in[2];
    const float* b1  = (const float*)d_in[3];
    const float* g1  = (const float*)d_in[4];
    const float* W2  = (const float*)d_in[5];
    const float* b2  = (const float*)d_in[6];
    const float* g2  = (const float*)d_in[7];
    const float* W3  = (const float*)d_in[8];
    const float* b3  = (const float*)d_in[9];
    float* out = (float*)d_out;

    const int table_blocks = TABLE_N / 16;            // 256
    const int prep_blocks  = (N_NODE + 127) / 128;    // 32
    table_prep_kernel<<<table_blocks + prep_blocks, 128>>>(
        pos, t, W1, b1, g1, W2, b2, g2, W3, b3);
    knn_eval_kernel<<<N_NODE / NQ, 256>>>(out);
}

// round 7
// speedup vs baseline: 1.8835x; 1.8835x over previous
#include <cuda_runtime.h>

#define N_NODE 4096
#define KNN 32
#define HIDDEN 128
#define RMS_EPS 1e-5f
#define TABLE_N 4096
#define NQ 8

__device__ float g_table[TABLE_N];
__device__ float4 g_pos4[N_NODE];

typedef unsigned long long u64;

// ---------------------------------------------------------------------------
// Kernel 1: table of s(u), u = r/(1+r), uniform grid; prep (pos -> float4)
// fused into the same launch as extra blocks.
// ---------------------------------------------------------------------------
__global__ void __launch_bounds__(128, 8)
table_prep_kernel(const float* __restrict__ pos,
                  const float* __restrict__ t,
                  const float* __restrict__ W1,
                  const float* __restrict__ b1,
                  const float* __restrict__ g1,
                  const float* __restrict__ W2,
                  const float* __restrict__ b2,
                  const float* __restrict__ g2,
                  const float* __restrict__ W3,
                  const float* __restrict__ b3) {
    const int tid = threadIdx.x;

    if (blockIdx.x >= TABLE_N / 16) {
        int j = (blockIdx.x - TABLE_N / 16) * 128 + tid;
        if (j < N_NODE)
            g_pos4[j] = make_float4(pos[3 * j], pos[3 * j + 1], pos[3 * j + 2], 0.0f);
        return;
    }

    __shared__ float h1s[4][HIDDEN * 4];
    __shared__ float sa[128], sc[128], sg1[128], sg2[128], sW3[128];
    __shared__ float sABC[3];
    __shared__ float sred[12];

    const int w = tid >> 5, lane = tid & 31;

    {
        const int k = tid;
        float t0 = t[0];
        float a = W1[2 * k];
        float c = fmaf(t0, W1[2 * k + 1], b1[k]);
        sa[k] = a; sc[k] = c;
        sg1[k] = g1[k]; sg2[k] = g2[k]; sW3[k] = W3[k];
        float pa = a * a, pb = a * c, pc = c * c;
        #pragma unroll
        for (int off = 16; off > 0; off >>= 1) {
            pa += __shfl_down_sync(0xffffffffu, pa, off);
            pb += __shfl_down_sync(0xffffffffu, pb, off);
            pc += __shfl_down_sync(0xffffffffu, pc, off);
        }
        if (lane == 0) { sred[w] = pa; sred[4 + w] = pb; sred[8 + w] = pc; }
    }
    __syncthreads();
    if (tid == 0) {
        const float inv = 1.0f / HIDDEN;
        sABC[0] = (sred[0] + sred[1] + sred[2] + sred[3]) * inv;
        sABC[1] = (sred[4] + sred[5] + sred[6] + sred[7]) * inv;
        sABC[2] = (sred[8] + sred[9] + sred[10] + sred[11]) * inv;
    }
    __syncthreads();

    const float A = sABC[0], Bc = sABC[1], C = sABC[2];
    const int s0 = blockIdx.x * 16 + w * 4;
    float* h1b = h1s[w];

    #pragma unroll
    for (int q = 0; q < 4; q++) {
        float u = (float)(s0 + q) * (1.0f / (float)(TABLE_N - 1));
        float om = 1.0f - u;
        float r = (om > 1e-8f) ? (u / om) : 1e9f;
        float den = fmaf(fmaf(r, A, 2.0f * Bc), r, C) + RMS_EPS;
        float scl = rsqrtf(den);
        #pragma unroll
        for (int p = 0; p < 4; p++) {
            int k = lane + 32 * p;
            float x = fmaf(r, sa[k], sc[k]);
            float v = x * scl * sg1[k];
            float h = v * (1.0f / (1.0f + __expf(-v)));
            h1b[k * 4 + q] = h;
        }
    }
    __syncwarp();

    float acc[4][4];
    #pragma unroll
    for (int p = 0; p < 4; p++)
        #pragma unroll
        for (int q = 0; q < 4; q++) acc[p][q] = 0.0f;

    const float4* wr0 = (const float4*)(W2 + (lane)      * HIDDEN);
    const float4* wr1 = (const float4*)(W2 + (lane + 32) * HIDDEN);
    const float4* wr2 = (const float4*)(W2 + (lane + 64) * HIDDEN);
    const float4* wr3 = (const float4*)(W2 + (lane + 96) * HIDDEN);
    #pragma unroll 2
    for (int kk = 0; kk < 32; kk++) {
        float4 w0 = __ldg(wr0 + kk), w1 = __ldg(wr1 + kk);
        float4 w2 = __ldg(wr2 + kk), w3 = __ldg(wr3 + kk);
        float w0a[4] = {w0.x, w0.y, w0.z, w0.w};
        float w1a[4] = {w1.x, w1.y, w1.z, w1.w};
        float w2a[4] = {w2.x, w2.y, w2.z, w2.w};
        float w3a[4] = {w3.x, w3.y, w3.z, w3.w};
        #pragma unroll
        for (int kq = 0; kq < 4; kq++) {
            float4 hv = *(const float4*)(h1b + (4 * kk + kq) * 4);
            float hva[4] = {hv.x, hv.y, hv.z, hv.w};
            #pragma unroll
            for (int q = 0; q < 4; q++) {
                acc[0][q] = fmaf(w0a[kq], hva[q], acc[0][q]);
                acc[1][q] = fmaf(w1a[kq], hva[q], acc[1][q]);
                acc[2][q] = fmaf(w2a[kq], hva[q], acc[2][q]);
                acc[3][q] = fmaf(w3a[kq], hva[q], acc[3][q]);
            }
        }
    }

    #pragma unroll
    for (int p = 0; p < 4; p++) {
        float bb = b2[lane + 32 * p];
        #pragma unroll
        for (int q = 0; q < 4; q++) acc[p][q] += bb;
    }

    float scl2[4];
    #pragma unroll
    for (int q = 0; q < 4; q++) {
        float ss = 0.0f;
        #pragma unroll
        for (int p = 0; p < 4; p++) ss = fmaf(acc[p][q], acc[p][q], ss);
        #pragma unroll
        for (int off = 16; off > 0; off >>= 1)
            ss += __shfl_xor_sync(0xffffffffu, ss, off);
        scl2[q] = rsqrtf(ss * (1.0f / HIDDEN) + RMS_EPS);
    }

    float dot[4] = {0.0f, 0.0f, 0.0f, 0.0f};
    #pragma unroll
    for (int p = 0; p < 4; p++) {
        int m = lane + 32 * p;
        float g = sg2[m], w3v = sW3[m];
        #pragma unroll
        for (int q = 0; q < 4; q++) {
            float v = acc[p][q] * scl2[q] * g;
            float h = v * (1.0f / (1.0f + __expf(-v)));
            dot[q] = fmaf(w3v, h, dot[q]);
        }
    }
    #pragma unroll
    for (int q = 0; q < 4; q++) {
        #pragma unroll
        for (int off = 16; off > 0; off >>= 1)
            dot[q] += __shfl_xor_sync(0xffffffffu, dot[q], off);
    }
    if (lane == 0) {
        float bb3 = b3[0];
        #pragma unroll
        for (int q = 0; q < 4; q++) g_table[s0 + q] = dot[q] + bb3;
    }
}

// ---------------------------------------------------------------------------
// Kernel 2: single-pass fused kNN + eval. 8 warps = 8 queries per block.
// Warp-cooperative online top-32: each lane holds ONE candidate key
// (distbits<<32 | idx); per 32-pair batch, lanes whose key is below the
// cached set-max are serialized through an exact replace-max insertion.
// Selected set = 32 smallest u64 keys = exact jax top_k (incl. tie-break).
// Eval: each lane's held key is one edge -> table lerp + accumulate.
// ---------------------------------------------------------------------------
__global__ void __launch_bounds__(256, 6)
knn_eval_kernel(float* __restrict__ out) {
    __shared__ float4 tile[512];                 // 8 KB

    const int tid = threadIdx.x;
    const int w = tid >> 5, lane = tid & 31;
    const int i = blockIdx.x * NQ + w;
    const float4 pi = g_pos4[i];
    const unsigned FULL = 0xffffffffu;

    u64 held = ~0ull;       // this lane's member of the current best-32 set
    u64 Tkey = ~0ull;       // cached upper bound of max(held) over the warp

    for (int tb = 0; tb < 8; tb++) {
        __syncthreads();
        tile[tid]       = g_pos4[tb * 512 + tid];
        tile[tid + 256] = g_pos4[tb * 512 + 256 + tid];
        __syncthreads();

        #pragma unroll 2
        for (int it = 0; it < 16; it++) {
            const int jl = it * 32 + lane;
            const int j = tb * 512 + jl;
            float4 q = tile[jl];
            float dx = pi.x - q.x, dy = pi.y - q.y, dz = pi.z - q.z;
            float d = fmaf(dx, dx, fmaf(dy, dy, dz * dz));
            unsigned bits = (j == i) ? 0x7f800000u : __float_as_uint(d);
            u64 key = ((u64)bits << 32) | (unsigned)j;

            unsigned m = __ballot_sync(FULL, key < Tkey);
            if (m) {
                u64 mx = 0;
                do {
                    const int src = __ffs(m) - 1;
                    m &= m - 1;
                    u64 k = __shfl_sync(FULL, key, src);
                    // current max of the held set (keys unique -> unique owner)
                    mx = held;
                    #pragma unroll
                    for (int off = 16; off > 0; off >>= 1) {
                        u64 o = __shfl_xor_sync(FULL, mx, off);
                        if (o > mx) mx = o;
                    }
                    if (k < mx && held == mx) held = k;
                } while (m);
                Tkey = mx;   // safe upper bound (pre-insertion max >= true max)
            }
        }
    }

    // ---- Eval: each lane's held key is one selected edge ----
    const float tscale = (float)(TABLE_N - 1);
    unsigned bb = (unsigned)(held >> 32);
    int j = (int)(held & 0xffffffffu);
    float4 q = g_pos4[j];
    float dx = pi.x - q.x, dy = pi.y - q.y, dz = pi.z - q.z;
    float r = __uint_as_float(bb);
    float u = r / (1.0f + r);
    float x = u * tscale;
    int i0 = (int)x; if (i0 > TABLE_N - 2) i0 = TABLE_N - 2;
    float f = x - (float)i0;
    float s0 = g_table[i0], s1 = g_table[i0 + 1];
    float sv = fmaf(f, s1 - s0, s0);

    float sx = dx * sv, sy = dy * sv, sz = dz * sv;
    #pragma unroll
    for (int off = 16; off > 0; off >>= 1) {
        sx += __shfl_down_sync(FULL, sx, off);
        sy += __shfl_down_sync(FULL, sy, off);
        sz += __shfl_down_sync(FULL, sz, off);
    }
    if (lane == 0) {
        const float invK = 1.0f / (float)KNN;
        out[3 * i]     = pi.x + sx * invK;
        out[3 * i + 1] = pi.y + sy * invK;
        out[3 * i + 2] = pi.z + sz * invK;
    }
}

// ---------------------------------------------------------------------------
// Launch
// ---------------------------------------------------------------------------
extern "C" void kernel_launch(void* const* d_in, const int* in_sizes, int n_in,
                              void* d_out, int out_size) {
    const float* pos = (const float*)d_in[0];
    const float* t   = (const float*)d_in[1];
    const float* W1  = (const float*)d_in[2];
    const float* b1  = (const float*)d_in[3];
    const float* g1  = (const float*)d_in[4];
    const float* W2  = (const float*)d_in[5];
    const float* b2  = (const float*)d_in[6];
    const float* g2  = (const float*)d_in[7];
    const float* W3  = (const float*)d_in[8];
    const float* b3  = (const float*)d_in[9];
    float* out = (float*)d_out;

    const int table_blocks = TABLE_N / 16;            // 256
    const int prep_blocks  = (N_NODE + 127) / 128;    // 32
    table_prep_kernel<<<table_blocks + prep_blocks, 128>>>(
        pos, t, W1, b1, g1, W2, b2, g2, W3, b3);
    knn_eval_kernel<<<N_NODE / NQ, 256>>>(out);
}